// round 4
// baseline (speedup 1.0000x reference)
#include <cuda_runtime.h>
#include <cstdint>
#include <math.h>

// ---------------------------------------------------------------------------
// HybridFeedForward: TT-factorized fc1 -> GELU(erf) -> TT-factorized fc2
// Strategy: reconstruct dense W1 (768x3072) / W2 (3072x768) from TT cores
// (cheaper than the TT einsum chain: ranks are large), then two tf32
// tensor-core GEMMs with fused bias (+ GELU on GEMM1).
// ---------------------------------------------------------------------------

#define NTOK 4096
#define D_IN 768
#define D_HID 3072

// ---- scratch (device globals; no allocation allowed) ----
__device__ float g_T12_1[384 * 24];
__device__ float g_T34_1[24 * 6144];
__device__ float g_T12_2[384 * 24];
__device__ float g_T34_2[24 * 6144];
__device__ float g_W1[D_IN * D_HID];     // 9.4 MB
__device__ float g_W2[D_HID * D_IN];     // 9.4 MB
__device__ float g_H[NTOK * D_HID];      // 50 MB

// ---------------------------------------------------------------------------
// Stage 1: T12[m, r2] = sum_r1 g1[i1,o1,r1] g2[r1,i2,o2,r2]
//          m = ((i1*I2 + i2)*O1 + o1)*O2 + o2          (384 x 24)
//          T34[r2, n] = sum_r3 g3[r2,i3,o3,r3] g4[r3,i4,o4]
//          n = ((i3*I4 + i4)*O3 + o3)*O4 + o4          (24 x 6144)
// ---------------------------------------------------------------------------
__global__ void build_tables(const float* __restrict__ g1, const float* __restrict__ g2,
                             const float* __restrict__ g3, const float* __restrict__ g4,
                             float* __restrict__ T12, float* __restrict__ T34,
                             int I1, int I2, int I3, int I4,
                             int O1, int O2, int O3, int O4)
{
    const int R1 = 12, R2 = 24, R3 = 12;
    int idx = blockIdx.x * blockDim.x + threadIdx.x;
    int n12 = I1 * I2 * O1 * O2 * R2;     // 9216
    int nN  = I3 * I4 * O3 * O4;          // 6144
    if (idx < n12) {
        int r2 = idx % R2; int m = idx / R2;
        int o2 = m % O2; int t = m / O2;
        int o1 = t % O1; t /= O1;
        int i2 = t % I2; int i1 = t / I2;
        float a0 = 0.f, a1 = 0.f, a2 = 0.f, a3 = 0.f;
        #pragma unroll
        for (int r1 = 0; r1 < R1; r1 += 4) {
            a0 += g1[(i1 * O1 + o1) * R1 + r1 + 0] * g2[(((r1 + 0) * I2 + i2) * O2 + o2) * R2 + r2];
            a1 += g1[(i1 * O1 + o1) * R1 + r1 + 1] * g2[(((r1 + 1) * I2 + i2) * O2 + o2) * R2 + r2];
            a2 += g1[(i1 * O1 + o1) * R1 + r1 + 2] * g2[(((r1 + 2) * I2 + i2) * O2 + o2) * R2 + r2];
            a3 += g1[(i1 * O1 + o1) * R1 + r1 + 3] * g2[(((r1 + 3) * I2 + i2) * O2 + o2) * R2 + r2];
        }
        T12[m * R2 + r2] = (a0 + a1) + (a2 + a3);
    } else {
        int j = idx - n12;
        if (j >= R2 * nN) return;
        int n = j % nN; int r2 = j / nN;
        int o4 = n % O4; int t = n / O4;
        int o3 = t % O3; t /= O3;
        int i4 = t % I4; int i3 = t / I4;
        float a0 = 0.f, a1 = 0.f, a2 = 0.f, a3 = 0.f;
        #pragma unroll
        for (int r3 = 0; r3 < R3; r3 += 4) {
            a0 += g3[((r2 * I3 + i3) * O3 + o3) * R3 + r3 + 0] * g4[((r3 + 0) * I4 + i4) * O4 + o4];
            a1 += g3[((r2 * I3 + i3) * O3 + o3) * R3 + r3 + 1] * g4[((r3 + 1) * I4 + i4) * O4 + o4];
            a2 += g3[((r2 * I3 + i3) * O3 + o3) * R3 + r3 + 2] * g4[((r3 + 2) * I4 + i4) * O4 + o4];
            a3 += g3[((r2 * I3 + i3) * O3 + o3) * R3 + r3 + 3] * g4[((r3 + 3) * I4 + i4) * O4 + o4];
        }
        T34[r2 * nN + n] = (a0 + a1) + (a2 + a3);
    }
}

// ---------------------------------------------------------------------------
// Stage 2: W[row, col] = sum_r2 T12[m, r2] * T34[r2, n]
//   row = (m / O12) * I34 + (n / O34),  col = (m % O12) * O34 + (n % O34)
// Block = 64 n-columns x 4 m-groups of 96. T12 fully in smem.
// ---------------------------------------------------------------------------
__global__ void __launch_bounds__(256)
build_w(const float* __restrict__ T12, const float* __restrict__ T34,
        float* __restrict__ W, int I34, int O34, int O12, int Ncols)
{
    __shared__ float s12[384 * 24];
    for (int i = threadIdx.x; i < 384 * 24 / 4; i += blockDim.x)
        ((float4*)s12)[i] = ((const float4*)T12)[i];
    __syncthreads();

    int nl = threadIdx.x & 63;
    int mg = threadIdx.x >> 6;
    int n  = blockIdx.x * 64 + nl;

    float t34[24];
    #pragma unroll
    for (int r = 0; r < 24; r++) t34[r] = T34[r * 6144 + n];

    int i3i4 = n / O34, o3o4 = n % O34;

    for (int m = mg * 96; m < mg * 96 + 96; m++) {
        const float4* p = (const float4*)&s12[m * 24];
        float a0 = 0.f, a1 = 0.f, a2 = 0.f, a3 = 0.f;
        #pragma unroll
        for (int q = 0; q < 6; q++) {
            float4 v = p[q];
            a0 += v.x * t34[q * 4 + 0];
            a1 += v.y * t34[q * 4 + 1];
            a2 += v.z * t34[q * 4 + 2];
            a3 += v.w * t34[q * 4 + 3];
        }
        int i1i2 = m / O12, o1o2 = m % O12;
        W[(i1i2 * I34 + i3i4) * Ncols + (o1o2 * O34 + o3o4)] = (a0 + a1) + (a2 + a3);
    }
}

// ---------------------------------------------------------------------------
// tf32 GEMM: C = act(A @ B + bias), A row-major MxK, B row-major KxN
// CTA tile 128x128, BK=16, 8 warps (2x4), warp tile 64x32, m16n8k8 mma.
// ---------------------------------------------------------------------------
__device__ __forceinline__ uint32_t f2tf(float x)
{
    uint32_t t;
    asm("cvt.rna.tf32.f32 %0, %1;" : "=r"(t) : "f"(x));
    return t;
}

__device__ __forceinline__ float4 cvt4(float4 v)
{
    float4 w;
    w.x = __uint_as_float(f2tf(v.x));
    w.y = __uint_as_float(f2tf(v.y));
    w.z = __uint_as_float(f2tf(v.z));
    w.w = __uint_as_float(f2tf(v.w));
    return w;
}

#define MMA_TF32(d, a, b)                                                     \
    asm volatile("mma.sync.aligned.m16n8k8.row.col.f32.tf32.tf32.f32 "        \
                 "{%0,%1,%2,%3}, {%4,%5,%6,%7}, {%8,%9}, {%0,%1,%2,%3};"      \
                 : "+f"(d[0]), "+f"(d[1]), "+f"(d[2]), "+f"(d[3])             \
                 : "r"(a[0]), "r"(a[1]), "r"(a[2]), "r"(a[3]),                \
                   "r"(b[0]), "r"(b[1]))

__device__ __forceinline__ float gelu_erf(float x)
{
    return 0.5f * x * (1.0f + erff(x * 0.70710678118654752f));
}

template <bool DO_GELU>
__global__ void __launch_bounds__(256, 2)
gemm_tf32(const float* __restrict__ A, const float* __restrict__ B,
          const float* __restrict__ bias, float* __restrict__ C,
          int M, int N, int K)
{
    __shared__ float As[2][128][20];   // pad 4: conflict-free frag loads
    __shared__ float Bs[2][16][136];   // pad 8: conflict-free frag loads

    const int tid  = threadIdx.x;
    const int lane = tid & 31;
    const int warp = tid >> 5;
    const int g    = lane >> 2;   // groupID
    const int t4   = lane & 3;
    const int wm   = warp & 1;    // 2 warps along M
    const int wn   = warp >> 1;   // 4 warps along N

    const int bm = blockIdx.y * 128;
    const int bn = blockIdx.x * 128;

    float acc[4][4][4];
    #pragma unroll
    for (int i = 0; i < 4; i++)
        #pragma unroll
        for (int j = 0; j < 4; j++)
            #pragma unroll
            for (int k = 0; k < 4; k++) acc[i][j][k] = 0.f;

    // global->smem thread mapping
    const int a_row0 = tid >> 2;              // 0..63
    const int a_col0 = (tid & 3) * 4;         // 0,4,8,12
    const int a_row1 = a_row0 + 64;
    const int b_k0   = tid >> 5;              // 0..7
    const int b_c0   = (tid & 31) * 4;        // 0..124
    const int b_k1   = b_k0 + 8;

    const int KT = K >> 4;

    // prologue: tile 0
    {
        const float* Ap = &A[(long)bm * K];
        const float* Bp = &B[(long)bn];
        float4 va0 = *(const float4*)&Ap[(long)a_row0 * K + a_col0];
        float4 va1 = *(const float4*)&Ap[(long)a_row1 * K + a_col0];
        float4 vb0 = *(const float4*)&Bp[(long)b_k0 * N + b_c0];
        float4 vb1 = *(const float4*)&Bp[(long)b_k1 * N + b_c0];
        *(float4*)&As[0][a_row0][a_col0] = cvt4(va0);
        *(float4*)&As[0][a_row1][a_col0] = cvt4(va1);
        *(float4*)&Bs[0][b_k0][b_c0]     = cvt4(vb0);
        *(float4*)&Bs[0][b_k1][b_c0]     = cvt4(vb1);
    }
    __syncthreads();

    int buf = 0;
    float4 na0, na1, nb0, nb1;

    for (int kt = 0; kt < KT; kt++) {
        const bool has_next = (kt + 1 < KT);
        if (has_next) {
            const float* Ap = &A[(long)bm * K + (kt + 1) * 16];
            const float* Bp = &B[(long)(kt + 1) * 16 * N + bn];
            na0 = *(const float4*)&Ap[(long)a_row0 * K + a_col0];
            na1 = *(const float4*)&Ap[(long)a_row1 * K + a_col0];
            nb0 = *(const float4*)&Bp[(long)b_k0 * N + b_c0];
            nb1 = *(const float4*)&Bp[(long)b_k1 * N + b_c0];
        }

        #pragma unroll
        for (int k8 = 0; k8 < 2; k8++) {
            uint32_t af[4][4];
            uint32_t bf[4][2];
            #pragma unroll
            for (int mt = 0; mt < 4; mt++) {
                int r = wm * 64 + mt * 16 + g;
                int kc = k8 * 8 + t4;
                af[mt][0] = __float_as_uint(As[buf][r][kc]);
                af[mt][1] = __float_as_uint(As[buf][r + 8][kc]);
                af[mt][2] = __float_as_uint(As[buf][r][kc + 4]);
                af[mt][3] = __float_as_uint(As[buf][r + 8][kc + 4]);
            }
            #pragma unroll
            for (int nt = 0; nt < 4; nt++) {
                int c = wn * 32 + nt * 8 + g;
                int kr = k8 * 8 + t4;
                bf[nt][0] = __float_as_uint(Bs[buf][kr][c]);
                bf[nt][1] = __float_as_uint(Bs[buf][kr + 4][c]);
            }
            #pragma unroll
            for (int mt = 0; mt < 4; mt++)
                #pragma unroll
                for (int nt = 0; nt < 4; nt++)
                    MMA_TF32(acc[mt][nt], af[mt], bf[nt]);
        }

        if (has_next) {
            int nxt = buf ^ 1;
            *(float4*)&As[nxt][a_row0][a_col0] = cvt4(na0);
            *(float4*)&As[nxt][a_row1][a_col0] = cvt4(na1);
            *(float4*)&Bs[nxt][b_k0][b_c0]     = cvt4(nb0);
            *(float4*)&Bs[nxt][b_k1][b_c0]     = cvt4(nb1);
        }
        __syncthreads();
        buf ^= 1;
    }

    // epilogue: bias (+ GELU), write C
    #pragma unroll
    for (int mt = 0; mt < 4; mt++) {
        int m = bm + wm * 64 + mt * 16 + g;
        #pragma unroll
        for (int nt = 0; nt < 4; nt++) {
            int n = bn + wn * 32 + nt * 8 + t4 * 2;
            float bv0 = bias[n], bv1 = bias[n + 1];
            float v0 = acc[mt][nt][0] + bv0;
            float v1 = acc[mt][nt][1] + bv1;
            float v2 = acc[mt][nt][2] + bv0;
            float v3 = acc[mt][nt][3] + bv1;
            if (DO_GELU) {
                v0 = gelu_erf(v0); v1 = gelu_erf(v1);
                v2 = gelu_erf(v2); v3 = gelu_erf(v3);
            }
            *(float2*)&C[(long)m * N + n]       = make_float2(v0, v1);
            *(float2*)&C[(long)(m + 8) * N + n] = make_float2(v2, v3);
        }
    }
}

// ---------------------------------------------------------------------------
// launch
// ---------------------------------------------------------------------------
static float* sym_addr(const void* sym)
{
    void* p = nullptr;
    cudaGetSymbolAddress(&p, sym);
    return (float*)p;
}

extern "C" void kernel_launch(void* const* d_in, const int* in_sizes, int n_in,
                              void* d_out, int out_size)
{
    const float* x   = (const float*)d_in[0];
    const float* g1a = (const float*)d_in[1];
    const float* g1b = (const float*)d_in[2];
    const float* g1c = (const float*)d_in[3];
    const float* g1d = (const float*)d_in[4];
    const float* b1  = (const float*)d_in[5];
    const float* g2a = (const float*)d_in[6];
    const float* g2b = (const float*)d_in[7];
    const float* g2c = (const float*)d_in[8];
    const float* g2d = (const float*)d_in[9];
    const float* b2  = (const float*)d_in[10];
    float* out = (float*)d_out;

    float* T12_1 = sym_addr(g_T12_1);
    float* T34_1 = sym_addr(g_T34_1);
    float* T12_2 = sym_addr(g_T12_2);
    float* T34_2 = sym_addr(g_T34_2);
    float* W1    = sym_addr(g_W1);
    float* W2    = sym_addr(g_W2);
    float* H     = sym_addr(g_H);

    // (9216 + 24*6144) elements = 156672 -> 612 blocks of 256
    build_tables<<<612, 256>>>(g1a, g1b, g1c, g1d, T12_1, T34_1,
                               4, 4, 6, 8, 4, 6, 8, 16);
    build_tables<<<612, 256>>>(g2a, g2b, g2c, g2d, T12_2, T34_2,
                               4, 6, 8, 16, 4, 4, 6, 8);

    // fc1: I34=48, O34=128, O12=24, Ncols=3072
    build_w<<<96, 256>>>(T12_1, T34_1, W1, 48, 128, 24, 3072);
    // fc2: I34=128, O34=48, O12=16, Ncols=768
    build_w<<<96, 256>>>(T12_2, T34_2, W2, 128, 48, 16, 768);

    // GEMM1: H = gelu(x @ W1 + b1)   (4096 x 3072, K=768)
    {
        dim3 grid(D_HID / 128, NTOK / 128);
        gemm_tf32<true><<<grid, 256>>>(x, W1, b1, H, NTOK, D_HID, D_IN);
    }
    // GEMM2: out = H @ W2 + b2       (4096 x 768, K=3072)
    {
        dim3 grid(D_IN / 128, NTOK / 128);
        gemm_tf32<false><<<grid, 256>>>(H, W2, b2, out, NTOK, D_IN, D_HID);
    }
}

// round 6
// speedup vs baseline: 2.0363x; 2.0363x over previous
#include <cuda_runtime.h>
#include <cuda_fp16.h>
#include <cstdint>
#include <math.h>

// ---------------------------------------------------------------------------
// HybridFeedForward: TT cores -> dense W1/W2 -> fp16 mma.sync GEMMs
//   GEMM1: H = gelu(x @ W1 + b1)   (4096 x 3072, K=768)
//   GEMM2: y = H @ W2 + b2         (4096 x 768,  K=3072)
// m16n8k16 fp16 MMA (fp32 accum), ldmatrix fragments, 4-stage cp.async ring.
// fp16 storage has the same 10-bit mantissa as tf32 (which passed at 4.2e-4).
// ---------------------------------------------------------------------------

#define NTOK 4096
#define D_IN 768
#define D_HID 3072
#define NSTAGE 4
#define STAGE_BYTES 16384            // A 8KB + B 8KB (128 x 32 halves each)
#define GEMM_SMEM (1024 + NSTAGE * STAGE_BYTES)

// ---- scratch (device globals; no allocation allowed) ----
__device__ float  g_T12_1[384 * 24];
__device__ float  g_T34_1[24 * 6144];
__device__ float  g_T12_2[384 * 24];
__device__ float  g_T34_2[24 * 6144];
__device__ float  g_W1[D_IN * D_HID];      // fp32 dense W1
__device__ float  g_W2[D_HID * D_IN];      // fp32 dense W2
__device__ __half g_W1t[D_HID * D_IN];     // W1^T  [3072][768]  half
__device__ __half g_W2t[D_IN * D_HID];     // W2^T  [768][3072]  half
__device__ __half g_xh[NTOK * D_IN];       // x in half
__device__ __half g_H[NTOK * D_HID];       // hidden, half

// ---------------------------------------------------------------------------
// helpers
// ---------------------------------------------------------------------------
__device__ __forceinline__ float gelu_erf(float x)
{
    return 0.5f * x * (1.0f + erff(x * 0.70710678118654752f));
}

__device__ __forceinline__ uint32_t smem_u32(const void* p)
{
    uint32_t a;
    asm("{ .reg .u64 t; cvta.to.shared.u64 t, %1; cvt.u32.u64 %0, t; }"
        : "=r"(a) : "l"(p));
    return a;
}

// ---------------------------------------------------------------------------
// Stage 1: TT core contraction tables
// ---------------------------------------------------------------------------
__global__ void build_tables(const float* __restrict__ g1, const float* __restrict__ g2,
                             const float* __restrict__ g3, const float* __restrict__ g4,
                             float* __restrict__ T12, float* __restrict__ T34,
                             int I1, int I2, int I3, int I4,
                             int O1, int O2, int O3, int O4)
{
    const int R1 = 12, R2 = 24, R3 = 12;
    int idx = blockIdx.x * blockDim.x + threadIdx.x;
    int n12 = I1 * I2 * O1 * O2 * R2;     // 9216
    int nN  = I3 * I4 * O3 * O4;          // 6144
    if (idx < n12) {
        int r2 = idx % R2; int m = idx / R2;
        int o2 = m % O2; int t = m / O2;
        int o1 = t % O1; t /= O1;
        int i2 = t % I2; int i1 = t / I2;
        float a0 = 0.f, a1 = 0.f, a2 = 0.f, a3 = 0.f;
        #pragma unroll
        for (int r1 = 0; r1 < R1; r1 += 4) {
            a0 += g1[(i1 * O1 + o1) * R1 + r1 + 0] * g2[(((r1 + 0) * I2 + i2) * O2 + o2) * R2 + r2];
            a1 += g1[(i1 * O1 + o1) * R1 + r1 + 1] * g2[(((r1 + 1) * I2 + i2) * O2 + o2) * R2 + r2];
            a2 += g1[(i1 * O1 + o1) * R1 + r1 + 2] * g2[(((r1 + 2) * I2 + i2) * O2 + o2) * R2 + r2];
            a3 += g1[(i1 * O1 + o1) * R1 + r1 + 3] * g2[(((r1 + 3) * I2 + i2) * O2 + o2) * R2 + r2];
        }
        T12[m * R2 + r2] = (a0 + a1) + (a2 + a3);
    } else {
        int j = idx - n12;
        if (j >= R2 * nN) return;
        int n = j % nN; int r2 = j / nN;
        int o4 = n % O4; int t = n / O4;
        int o3 = t % O3; t /= O3;
        int i4 = t % I4; int i3 = t / I4;
        float a0 = 0.f, a1 = 0.f, a2 = 0.f, a3 = 0.f;
        #pragma unroll
        for (int r3 = 0; r3 < R3; r3 += 4) {
            a0 += g3[((r2 * I3 + i3) * O3 + o3) * R3 + r3 + 0] * g4[((r3 + 0) * I4 + i4) * O4 + o4];
            a1 += g3[((r2 * I3 + i3) * O3 + o3) * R3 + r3 + 1] * g4[((r3 + 1) * I4 + i4) * O4 + o4];
            a2 += g3[((r2 * I3 + i3) * O3 + o3) * R3 + r3 + 2] * g4[((r3 + 2) * I4 + i4) * O4 + o4];
            a3 += g3[((r2 * I3 + i3) * O3 + o3) * R3 + r3 + 3] * g4[((r3 + 3) * I4 + i4) * O4 + o4];
        }
        T34[r2 * nN + n] = (a0 + a1) + (a2 + a3);
    }
}

// ---------------------------------------------------------------------------
// Stage 2: W[row, col] = sum_r2 T12[m,r2] * T34[r2,n]  (4-way m-split grid)
// ---------------------------------------------------------------------------
__global__ void __launch_bounds__(256)
build_w(const float* __restrict__ T12, const float* __restrict__ T34,
        float* __restrict__ W, int I34, int O34, int O12, int Ncols)
{
    __shared__ float s12[96 * 24];
    int mbase = blockIdx.y * 96;
    for (int i = threadIdx.x; i < 96 * 24 / 4; i += 256)
        ((float4*)s12)[i] = ((const float4*)(T12 + mbase * 24))[i];
    __syncthreads();

    int nl = threadIdx.x & 63;
    int mg = threadIdx.x >> 6;
    int n  = blockIdx.x * 64 + nl;

    float t34[24];
    #pragma unroll
    for (int r = 0; r < 24; r++) t34[r] = T34[r * 6144 + n];

    int i3i4 = n / O34, o3o4 = n % O34;

    for (int mm = mg * 24; mm < mg * 24 + 24; mm++) {
        const float4* p = (const float4*)&s12[mm * 24];
        float a0 = 0.f, a1 = 0.f, a2 = 0.f, a3 = 0.f;
        #pragma unroll
        for (int q = 0; q < 6; q++) {
            float4 v = p[q];
            a0 += v.x * t34[q * 4 + 0];
            a1 += v.y * t34[q * 4 + 1];
            a2 += v.z * t34[q * 4 + 2];
            a3 += v.w * t34[q * 4 + 3];
        }
        int m = mbase + mm;
        int i1i2 = m / O12, o1o2 = m % O12;
        W[(i1i2 * I34 + i3i4) * Ncols + (o1o2 * O34 + o3o4)] = (a0 + a1) + (a2 + a3);
    }
}

// ---------------------------------------------------------------------------
// transpose + fp16 convert:  D[c, r] = half(S[r, c]),  S is R x C fp32
// ---------------------------------------------------------------------------
__global__ void __launch_bounds__(256)
transpose_cvt_h(const float* __restrict__ S, __half* __restrict__ D, int R, int C)
{
    __shared__ float tile[32][33];
    int c0 = blockIdx.x * 32, r0 = blockIdx.y * 32;
    int tx = threadIdx.x, ty = threadIdx.y;
    #pragma unroll
    for (int i = 0; i < 32; i += 8)
        tile[ty + i][tx] = S[(long)(r0 + ty + i) * C + c0 + tx];
    __syncthreads();
    #pragma unroll
    for (int i = 0; i < 32; i += 8)
        D[(long)(c0 + ty + i) * R + r0 + tx] = __float2half_rn(tile[tx][ty + i]);
}

// ---------------------------------------------------------------------------
// fp32 -> fp16 vector convert (x)
// ---------------------------------------------------------------------------
__global__ void cvt_f2h(const float4* __restrict__ in, __half2* __restrict__ out, int n4)
{
    int i = blockIdx.x * blockDim.x + threadIdx.x;
    for (; i < n4; i += gridDim.x * blockDim.x) {
        float4 v = in[i];
        out[2 * i + 0] = __floats2half2_rn(v.x, v.y);
        out[2 * i + 1] = __floats2half2_rn(v.z, v.w);
    }
}

// ---------------------------------------------------------------------------
// fp16 GEMM: C = act(A @ Bt^T + bias)
//   A:  M x K row-major half, Bt: N x K row-major half
//   CTA tile 128x128, BK=32, 4-stage cp.async, 8 warps (2 x 4), warp 64x32.
// smem per stage: A[128][32] half (64B rows) + B[128][32] half, XOR-swizzled:
//   byte = row*64 + (chunk ^ ((row>>1)&3))*16        (chunk = k-16B index)
// ---------------------------------------------------------------------------
#define MMA_F16(d, a, b)                                                      \
    asm volatile("mma.sync.aligned.m16n8k16.row.col.f32.f16.f16.f32 "         \
                 "{%0,%1,%2,%3}, {%4,%5,%6,%7}, {%8,%9}, {%0,%1,%2,%3};"      \
                 : "+f"(d[0]), "+f"(d[1]), "+f"(d[2]), "+f"(d[3])             \
                 : "r"(a[0]), "r"(a[1]), "r"(a[2]), "r"(a[3]),                \
                   "r"(b[0]), "r"(b[1]))

#define LDSM_X4(r0, r1, r2, r3, addr)                                         \
    asm volatile("ldmatrix.sync.aligned.m8n8.x4.shared.b16 {%0,%1,%2,%3}, [%4];" \
                 : "=r"(r0), "=r"(r1), "=r"(r2), "=r"(r3) : "r"(addr))

template <bool GELU, bool HALF_OUT>
__global__ void __launch_bounds__(256, 2)
gemm_h(const __half* __restrict__ A, const __half* __restrict__ Bt,
       const float* __restrict__ bias, void* __restrict__ Cv,
       int M, int N, int K)
{
    extern __shared__ char dsm[];
    uint32_t stg = (smem_u32(dsm) + 1023) & ~1023u;

    const int tid  = threadIdx.x;
    const int lane = tid & 31;
    const int wid  = tid >> 5;
    const int wm   = wid & 1;          // 2 warps along M (64 each)
    const int wn   = wid >> 1;         // 4 warps along N (32 each)
    const int bm   = blockIdx.y * 128;
    const int bn   = blockIdx.x * 128;
    const int T    = K >> 5;

    // ---- global->smem mapping: row = tid>>1, two 16B chunks each ----
    const int row_l = tid >> 1;
    const int jj    = tid & 1;
    const uint32_t sw = (row_l >> 1) & 3;
    const __half* Ag = A  + (size_t)(bm + row_l) * K;
    const __half* Bg = Bt + (size_t)(bn + row_l) * K;
    uint32_t st_off[2];
    #pragma unroll
    for (int q = 0; q < 2; q++) {
        uint32_t c = (jj << 1) + q;
        st_off[q] = row_l * 64 + ((c ^ sw) << 4);
    }

    #define LOADST(t, s)                                                          \
    do {                                                                          \
        const __half* ap = Ag + (t) * 32 + ((jj << 1)) * 8;                       \
        const __half* bp = Bg + (t) * 32 + ((jj << 1)) * 8;                       \
        uint32_t sa = stg + (s) * STAGE_BYTES;                                    \
        uint32_t sb = sa + 8192;                                                  \
        _Pragma("unroll")                                                         \
        for (int q = 0; q < 2; q++) {                                             \
            asm volatile("cp.async.cg.shared.global [%0], [%1], 16;"              \
                         :: "r"(sa + st_off[q]), "l"(ap + q * 8) : "memory");     \
            asm volatile("cp.async.cg.shared.global [%0], [%1], 16;"              \
                         :: "r"(sb + st_off[q]), "l"(bp + q * 8) : "memory");     \
        }                                                                         \
    } while (0)

    // ---- fragment address components ----
    const int lr      = lane & 7;
    const int mi      = lane >> 3;
    const int a_row0  = wm * 64 + ((mi & 1) << 3) + lr;
    const int a_kcbit = (mi >> 1) & 1;
    const int b_row0  = wn * 32 + ((mi >> 1) << 3) + lr;
    const int b_kcbit = mi & 1;

    float acc[4][4][4];
    #pragma unroll
    for (int i = 0; i < 4; i++)
        #pragma unroll
        for (int j = 0; j < 4; j++)
            #pragma unroll
            for (int k = 0; k < 4; k++) acc[i][j][k] = 0.f;

    // ---- prologue: stages 0..NSTAGE-2 ----
    #pragma unroll
    for (int s = 0; s < NSTAGE - 1; s++) {
        LOADST(s, s);
        asm volatile("cp.async.commit_group;" ::: "memory");
    }

    for (int t = 0; t < T; t++) {
        asm volatile("cp.async.wait_group %0;" :: "n"(NSTAGE - 2) : "memory");
        __syncthreads();

        int tl = t + NSTAGE - 1;
        if (tl < T) LOADST(tl, tl & (NSTAGE - 1));
        asm volatile("cp.async.commit_group;" ::: "memory");

        uint32_t sa = stg + (t & (NSTAGE - 1)) * STAGE_BYTES;
        uint32_t sb = sa + 8192;

        #pragma unroll
        for (int ks = 0; ks < 2; ks++) {
            uint32_t af[4][4];
            #pragma unroll
            for (int mt = 0; mt < 4; mt++) {
                int r = a_row0 + mt * 16;
                uint32_t kc = (uint32_t)((ks << 1) | a_kcbit);
                uint32_t addr = sa + r * 64 + ((kc ^ ((r >> 1) & 3)) << 4);
                LDSM_X4(af[mt][0], af[mt][1], af[mt][2], af[mt][3], addr);
            }
            uint32_t bf[4][2];
            #pragma unroll
            for (int p = 0; p < 2; p++) {
                int r = b_row0 + p * 16;
                uint32_t kc = (uint32_t)((ks << 1) | b_kcbit);
                uint32_t addr = sb + r * 64 + ((kc ^ ((r >> 1) & 3)) << 4);
                uint32_t r0, r1, r2, r3;
                LDSM_X4(r0, r1, r2, r3, addr);
                bf[2 * p][0] = r0; bf[2 * p][1] = r1;
                bf[2 * p + 1][0] = r2; bf[2 * p + 1][1] = r3;
            }
            #pragma unroll
            for (int mt = 0; mt < 4; mt++)
                #pragma unroll
                for (int nt = 0; nt < 4; nt++)
                    MMA_F16(acc[mt][nt], af[mt], bf[nt]);
        }
    }

    // ---- epilogue: bias (+GELU), store ----
    const int g  = lane >> 2;
    const int t4 = lane & 3;
    #pragma unroll
    for (int mt = 0; mt < 4; mt++) {
        int m = bm + wm * 64 + mt * 16 + g;
        #pragma unroll
        for (int nt = 0; nt < 4; nt++) {
            int n = bn + wn * 32 + nt * 8 + t4 * 2;
            float bv0 = bias[n], bv1 = bias[n + 1];
            float v0 = acc[mt][nt][0] + bv0;
            float v1 = acc[mt][nt][1] + bv1;
            float v2 = acc[mt][nt][2] + bv0;
            float v3 = acc[mt][nt][3] + bv1;
            if (GELU) {
                v0 = gelu_erf(v0); v1 = gelu_erf(v1);
                v2 = gelu_erf(v2); v3 = gelu_erf(v3);
            }
            if (HALF_OUT) {
                __half* Ch = (__half*)Cv;
                *(__half2*)&Ch[(size_t)m * N + n]       = __floats2half2_rn(v0, v1);
                *(__half2*)&Ch[(size_t)(m + 8) * N + n] = __floats2half2_rn(v2, v3);
            } else {
                float* Cf = (float*)Cv;
                *(float2*)&Cf[(size_t)m * N + n]       = make_float2(v0, v1);
                *(float2*)&Cf[(size_t)(m + 8) * N + n] = make_float2(v2, v3);
            }
        }
    }
}

// ---------------------------------------------------------------------------
// launch
// ---------------------------------------------------------------------------
static void* sym_addr(const void* sym)
{
    void* p = nullptr;
    cudaGetSymbolAddress(&p, sym);
    return p;
}

extern "C" void kernel_launch(void* const* d_in, const int* in_sizes, int n_in,
                              void* d_out, int out_size)
{
    const float* x   = (const float*)d_in[0];
    const float* g1a = (const float*)d_in[1];
    const float* g1b = (const float*)d_in[2];
    const float* g1c = (const float*)d_in[3];
    const float* g1d = (const float*)d_in[4];
    const float* b1  = (const float*)d_in[5];
    const float* g2a = (const float*)d_in[6];
    const float* g2b = (const float*)d_in[7];
    const float* g2c = (const float*)d_in[8];
    const float* g2d = (const float*)d_in[9];
    const float* b2  = (const float*)d_in[10];
    float* out = (float*)d_out;

    float*  T12_1 = (float*)sym_addr(g_T12_1);
    float*  T34_1 = (float*)sym_addr(g_T34_1);
    float*  T12_2 = (float*)sym_addr(g_T12_2);
    float*  T34_2 = (float*)sym_addr(g_T34_2);
    float*  W1    = (float*)sym_addr(g_W1);
    float*  W2    = (float*)sym_addr(g_W2);
    __half* W1t   = (__half*)sym_addr(g_W1t);
    __half* W2t   = (__half*)sym_addr(g_W2t);
    __half* xh    = (__half*)sym_addr(g_xh);
    __half* H     = (__half*)sym_addr(g_H);

    static int attr_set = 0;
    cudaFuncSetAttribute(gemm_h<true, true>,
                         cudaFuncAttributeMaxDynamicSharedMemorySize, GEMM_SMEM);
    cudaFuncSetAttribute(gemm_h<false, false>,
                         cudaFuncAttributeMaxDynamicSharedMemorySize, GEMM_SMEM);
    (void)attr_set;

    build_tables<<<612, 256>>>(g1a, g1b, g1c, g1d, T12_1, T34_1,
                               4, 4, 6, 8, 4, 6, 8, 16);
    build_tables<<<612, 256>>>(g2a, g2b, g2c, g2d, T12_2, T34_2,
                               4, 6, 8, 16, 4, 4, 6, 8);

    {
        dim3 grid(96, 4);
        build_w<<<grid, 256>>>(T12_1, T34_1, W1, 48, 128, 24, 3072);
        build_w<<<grid, 256>>>(T12_2, T34_2, W2, 128, 48, 16, 768);
    }

    {
        dim3 blk(32, 8);
        dim3 gA(D_HID / 32, D_IN / 32);   // W1 (768x3072) -> W1t (3072x768)
        transpose_cvt_h<<<gA, blk>>>(W1, W1t, D_IN, D_HID);
        dim3 gB(D_IN / 32, D_HID / 32);   // W2 (3072x768) -> W2t (768x3072)
        transpose_cvt_h<<<gB, blk>>>(W2, W2t, D_HID, D_IN);
    }

    cvt_f2h<<<1024, 256>>>((const float4*)x, (__half2*)xh, NTOK * D_IN / 4);

    // GEMM1: H = gelu(xh @ W1 + b1)
    {
        dim3 grid(D_HID / 128, NTOK / 128);
        gemm_h<true, true><<<grid, 256, GEMM_SMEM>>>(xh, W1t, b1, H,
                                                     NTOK, D_HID, D_IN);
    }
    // GEMM2: out = H @ W2 + b2
    {
        dim3 grid(D_IN / 128, NTOK / 128);
        gemm_h<false, false><<<grid, 256, GEMM_SMEM>>>(H, W2t, b2, out,
                                                       NTOK, D_IN, D_HID);
    }
}

// round 8
// speedup vs baseline: 2.1582x; 1.0599x over previous
#include <cuda_runtime.h>
#include <cuda_fp16.h>
#include <cstdint>
#include <math.h>

// ---------------------------------------------------------------------------
// HybridFeedForward: TT cores -> dense W1/W2 -> fp16 mma.sync GEMMs
//   GEMM1: H = gelu(x @ W1 + b1)   (4096 x 3072, K=768)   tile 128x128
//   GEMM2: y = H @ W2 + b2         (4096 x 768,  K=3072)  tile 128x96
// m16n8k16 fp16 MMA (fp32 accum), ldmatrix fragments, 4-stage cp.async ring.
// ---------------------------------------------------------------------------

#define NTOK 4096
#define D_IN 768
#define D_HID 3072
#define NSTAGE 4

// ---- scratch (device globals; no allocation allowed) ----
__device__ float  g_T12_1[384 * 24];
__device__ float  g_T34_1[24 * 6144];
__device__ float  g_T12_2[384 * 24];
__device__ float  g_T34_2[24 * 6144];
__device__ float  g_W1[D_IN * D_HID];      // fp32 dense W1
__device__ float  g_W2[D_HID * D_IN];      // fp32 dense W2
__device__ __half g_W1t[D_HID * D_IN];     // W1^T  [3072][768]  half
__device__ __half g_W2t[D_IN * D_HID];     // W2^T  [768][3072]  half
__device__ __half g_xh[NTOK * D_IN];       // x in half
__device__ __half g_H[NTOK * D_HID];       // hidden, half

// ---------------------------------------------------------------------------
// helpers
// ---------------------------------------------------------------------------
__device__ __forceinline__ float gelu_erf(float x)
{
    return 0.5f * x * (1.0f + erff(x * 0.70710678118654752f));
}

__device__ __forceinline__ uint32_t smem_u32(const void* p)
{
    uint32_t a;
    asm("{ .reg .u64 t; cvta.to.shared.u64 t, %1; cvt.u32.u64 %0, t; }"
        : "=r"(a) : "l"(p));
    return a;
}

// ---------------------------------------------------------------------------
// Stage 1: TT core contraction tables
// ---------------------------------------------------------------------------
__global__ void build_tables(const float* __restrict__ g1, const float* __restrict__ g2,
                             const float* __restrict__ g3, const float* __restrict__ g4,
                             float* __restrict__ T12, float* __restrict__ T34,
                             int I1, int I2, int I3, int I4,
                             int O1, int O2, int O3, int O4)
{
    const int R1 = 12, R2 = 24, R3 = 12;
    int idx = blockIdx.x * blockDim.x + threadIdx.x;
    int n12 = I1 * I2 * O1 * O2 * R2;     // 9216
    int nN  = I3 * I4 * O3 * O4;          // 6144
    if (idx < n12) {
        int r2 = idx % R2; int m = idx / R2;
        int o2 = m % O2; int t = m / O2;
        int o1 = t % O1; t /= O1;
        int i2 = t % I2; int i1 = t / I2;
        float a0 = 0.f, a1 = 0.f, a2 = 0.f, a3 = 0.f;
        #pragma unroll
        for (int r1 = 0; r1 < R1; r1 += 4) {
            a0 += g1[(i1 * O1 + o1) * R1 + r1 + 0] * g2[(((r1 + 0) * I2 + i2) * O2 + o2) * R2 + r2];
            a1 += g1[(i1 * O1 + o1) * R1 + r1 + 1] * g2[(((r1 + 1) * I2 + i2) * O2 + o2) * R2 + r2];
            a2 += g1[(i1 * O1 + o1) * R1 + r1 + 2] * g2[(((r1 + 2) * I2 + i2) * O2 + o2) * R2 + r2];
            a3 += g1[(i1 * O1 + o1) * R1 + r1 + 3] * g2[(((r1 + 3) * I2 + i2) * O2 + o2) * R2 + r2];
        }
        T12[m * R2 + r2] = (a0 + a1) + (a2 + a3);
    } else {
        int j = idx - n12;
        if (j >= R2 * nN) return;
        int n = j % nN; int r2 = j / nN;
        int o4 = n % O4; int t = n / O4;
        int o3 = t % O3; t /= O3;
        int i4 = t % I4; int i3 = t / I4;
        float a0 = 0.f, a1 = 0.f, a2 = 0.f, a3 = 0.f;
        #pragma unroll
        for (int r3 = 0; r3 < R3; r3 += 4) {
            a0 += g3[((r2 * I3 + i3) * O3 + o3) * R3 + r3 + 0] * g4[((r3 + 0) * I4 + i4) * O4 + o4];
            a1 += g3[((r2 * I3 + i3) * O3 + o3) * R3 + r3 + 1] * g4[((r3 + 1) * I4 + i4) * O4 + o4];
            a2 += g3[((r2 * I3 + i3) * O3 + o3) * R3 + r3 + 2] * g4[((r3 + 2) * I4 + i4) * O4 + o4];
            a3 += g3[((r2 * I3 + i3) * O3 + o3) * R3 + r3 + 3] * g4[((r3 + 3) * I4 + i4) * O4 + o4];
        }
        T34[r2 * nN + n] = (a0 + a1) + (a2 + a3);
    }
}

// ---------------------------------------------------------------------------
// Stage 2: W[row, col] = sum_r2 T12[m,r2] * T34[r2,n]
//   strength-reduced indexing: no per-iter div/mod, incremental address.
// ---------------------------------------------------------------------------
__global__ void __launch_bounds__(256)
build_w(const float* __restrict__ T12, const float* __restrict__ T34,
        float* __restrict__ W, int I34, int O34, int O12, int Ncols)
{
    __shared__ float s12[96 * 24];
    int mbase = blockIdx.y * 96;
    for (int i = threadIdx.x; i < 96 * 24 / 4; i += 256)
        ((float4*)s12)[i] = ((const float4*)(T12 + mbase * 24))[i];
    __syncthreads();

    int nl = threadIdx.x & 63;
    int mg = threadIdx.x >> 6;
    int n  = blockIdx.x * 64 + nl;

    float t34[24];
    #pragma unroll
    for (int r = 0; r < 24; r++) t34[r] = T34[r * 6144 + n];

    int i3i4 = n / O34, o3o4 = n % O34;

    int m0    = mbase + mg * 24;
    int i1i2  = m0 / O12;
    int o1o2  = m0 % O12;
    long addr = (long)(i1i2 * I34 + i3i4) * Ncols + o1o2 * O34 + o3o4;
    const long dWrap = (long)I34 * Ncols - (long)(O12 - 1) * O34;

    const float4* p = (const float4*)&s12[(mg * 24) * 24];
    #pragma unroll 4
    for (int mm = 0; mm < 24; mm++) {
        float a0 = 0.f, a1 = 0.f, a2 = 0.f, a3 = 0.f;
        #pragma unroll
        for (int q = 0; q < 6; q++) {
            float4 v = p[q];
            a0 += v.x * t34[q * 4 + 0];
            a1 += v.y * t34[q * 4 + 1];
            a2 += v.z * t34[q * 4 + 2];
            a3 += v.w * t34[q * 4 + 3];
        }
        p += 6;
        W[addr] = (a0 + a1) + (a2 + a3);
        o1o2++;
        if (o1o2 == O12) { o1o2 = 0; addr += dWrap; }
        else             { addr += O34; }
    }
}

// ---------------------------------------------------------------------------
// transpose + fp16 convert:  D[c, r] = half(S[r, c]),  S is R x C fp32
// ---------------------------------------------------------------------------
__global__ void __launch_bounds__(256)
transpose_cvt_h(const float* __restrict__ S, __half* __restrict__ D, int R, int C)
{
    __shared__ float tile[32][33];
    int c0 = blockIdx.x * 32, r0 = blockIdx.y * 32;
    int tx = threadIdx.x, ty = threadIdx.y;
    #pragma unroll
    for (int i = 0; i < 32; i += 8)
        tile[ty + i][tx] = S[(long)(r0 + ty + i) * C + c0 + tx];
    __syncthreads();
    #pragma unroll
    for (int i = 0; i < 32; i += 8)
        D[(long)(c0 + ty + i) * R + r0 + tx] = __float2half_rn(tile[tx][ty + i]);
}

// ---------------------------------------------------------------------------
// fp32 -> fp16 vector convert (x)
// ---------------------------------------------------------------------------
__global__ void cvt_f2h(const float4* __restrict__ in, __half2* __restrict__ out, int n4)
{
    int i = blockIdx.x * blockDim.x + threadIdx.x;
    for (; i < n4; i += gridDim.x * blockDim.x) {
        float4 v = in[i];
        out[2 * i + 0] = __floats2half2_rn(v.x, v.y);
        out[2 * i + 1] = __floats2half2_rn(v.z, v.w);
    }
}

// ---------------------------------------------------------------------------
// fp16 GEMM: C = act(A @ Bt^T + bias)
//   A:  M x K row-major half, Bt: N x K row-major half
//   CTA tile 128 x BN, BK=32, 4-stage cp.async, 8 warps (2m x 4n).
// smem per stage: A[128][32] half (64B rows) + B[BN][32] half, XOR-swizzled:
//   byte = row*64 + (chunk ^ ((row>>1)&3))*16
// ---------------------------------------------------------------------------
#define MMA_F16(d, a, b)                                                      \
    asm volatile("mma.sync.aligned.m16n8k16.row.col.f32.f16.f16.f32 "         \
                 "{%0,%1,%2,%3}, {%4,%5,%6,%7}, {%8,%9}, {%0,%1,%2,%3};"      \
                 : "+f"(d[0]), "+f"(d[1]), "+f"(d[2]), "+f"(d[3])             \
                 : "r"(a[0]), "r"(a[1]), "r"(a[2]), "r"(a[3]),                \
                   "r"(b[0]), "r"(b[1]))

#define LDSM_X4(r0, r1, r2, r3, addr)                                         \
    asm volatile("ldmatrix.sync.aligned.m8n8.x4.shared.b16 {%0,%1,%2,%3}, [%4];" \
                 : "=r"(r0), "=r"(r1), "=r"(r2), "=r"(r3) : "r"(addr))

#define LDSM_X2(r0, r1, addr)                                                 \
    asm volatile("ldmatrix.sync.aligned.m8n8.x2.shared.b16 {%0,%1}, [%2];"    \
                 : "=r"(r0), "=r"(r1) : "r"(addr))

template <int BN, bool GELU, bool HALF_OUT>
__global__ void __launch_bounds__(256, 2)
gemm_h(const __half* __restrict__ A, const __half* __restrict__ Bt,
       const float* __restrict__ bias, void* __restrict__ Cv,
       int M, int N, int K)
{
    constexpr int SBYTES = 8192 + BN * 64;   // A stage + B stage
    constexpr int NFRAG  = BN / 32;          // n-fragments per warp (8 wide)
    constexpr int WN     = BN / 4;           // warp n-tile

    extern __shared__ char dsm[];
    uint32_t stg = (smem_u32(dsm) + 1023) & ~1023u;

    const int tid  = threadIdx.x;
    const int lane = tid & 31;
    const int wid  = tid >> 5;
    const int wm   = wid & 1;          // 2 warps along M (64 each)
    const int wn   = wid >> 1;         // 4 warps along N (WN each)
    const int bm   = blockIdx.y * 128;
    const int bn   = blockIdx.x * BN;
    const int T    = K >> 5;

    // ---- global->smem mapping: row = tid>>1, two 16B chunks each ----
    const int row_l = tid >> 1;
    const int jj    = tid & 1;
    const uint32_t sw = (row_l >> 1) & 3;
    const __half* Ag = A  + (size_t)(bm + row_l) * K;
    const __half* Bg = Bt + (size_t)(bn + row_l) * K;
    uint32_t st_off[2];
    #pragma unroll
    for (int q = 0; q < 2; q++) {
        uint32_t c = (jj << 1) + q;
        st_off[q] = row_l * 64 + ((c ^ sw) << 4);
    }
    const bool do_b = (BN == 128) || (row_l < BN);

    #define LOADST(t, s)                                                          \
    do {                                                                          \
        const __half* ap = Ag + (t) * 32 + (jj << 1) * 8;                         \
        const __half* bp = Bg + (t) * 32 + (jj << 1) * 8;                         \
        uint32_t sa = stg + (s) * SBYTES;                                         \
        uint32_t sb = sa + 8192;                                                  \
        _Pragma("unroll")                                                         \
        for (int q = 0; q < 2; q++) {                                             \
            asm volatile("cp.async.cg.shared.global [%0], [%1], 16;"              \
                         :: "r"(sa + st_off[q]), "l"(ap + q * 8) : "memory");     \
            if (do_b)                                                             \
                asm volatile("cp.async.cg.shared.global [%0], [%1], 16;"          \
                             :: "r"(sb + st_off[q]), "l"(bp + q * 8) : "memory"); \
        }                                                                         \
    } while (0)

    // ---- fragment address components ----
    const int lr      = lane & 7;
    const int mi      = lane >> 3;
    const int a_row0  = wm * 64 + ((mi & 1) << 3) + lr;
    const int a_kcbit = (mi >> 1) & 1;
    const int b_row0  = wn * WN + ((mi >> 1) << 3) + lr;
    const int b_kcbit = mi & 1;
    const int b2_row  = wn * WN + (NFRAG & ~1) * 8 + lr;   // last-frag x2 base
    const int b2_kcb  = (lane >> 3) & 1;

    float acc[4][NFRAG][4];
    #pragma unroll
    for (int i = 0; i < 4; i++)
        #pragma unroll
        for (int j = 0; j < NFRAG; j++)
            #pragma unroll
            for (int k = 0; k < 4; k++) acc[i][j][k] = 0.f;

    // ---- prologue: stages 0..NSTAGE-2 ----
    #pragma unroll
    for (int s = 0; s < NSTAGE - 1; s++) {
        LOADST(s, s);
        asm volatile("cp.async.commit_group;" ::: "memory");
    }

    for (int t = 0; t < T; t++) {
        asm volatile("cp.async.wait_group %0;" :: "n"(NSTAGE - 2) : "memory");
        __syncthreads();

        int tl = t + NSTAGE - 1;
        if (tl < T) LOADST(tl, tl & (NSTAGE - 1));
        asm volatile("cp.async.commit_group;" ::: "memory");

        uint32_t sa = stg + (t & (NSTAGE - 1)) * SBYTES;
        uint32_t sb = sa + 8192;

        #pragma unroll
        for (int ks = 0; ks < 2; ks++) {
            uint32_t af[4][4];
            #pragma unroll
            for (int mt = 0; mt < 4; mt++) {
                int r = a_row0 + mt * 16;
                uint32_t kc = (uint32_t)((ks << 1) | a_kcbit);
                uint32_t addr = sa + r * 64 + ((kc ^ ((r >> 1) & 3)) << 4);
                LDSM_X4(af[mt][0], af[mt][1], af[mt][2], af[mt][3], addr);
            }
            uint32_t bf[NFRAG][2];
            #pragma unroll
            for (int p = 0; p < NFRAG / 2; p++) {
                int r = b_row0 + p * 16;
                uint32_t kc = (uint32_t)((ks << 1) | b_kcbit);
                uint32_t addr = sb + r * 64 + ((kc ^ ((r >> 1) & 3)) << 4);
                uint32_t r0, r1, r2, r3;
                LDSM_X4(r0, r1, r2, r3, addr);
                bf[2 * p][0] = r0; bf[2 * p][1] = r1;
                bf[2 * p + 1][0] = r2; bf[2 * p + 1][1] = r3;
            }
            if (NFRAG & 1) {
                int r = b2_row;
                uint32_t kc = (uint32_t)((ks << 1) | b2_kcb);
                uint32_t addr = sb + r * 64 + ((kc ^ ((r >> 1) & 3)) << 4);
                LDSM_X2(bf[NFRAG - 1][0], bf[NFRAG - 1][1], addr);
            }
            #pragma unroll
            for (int mt = 0; mt < 4; mt++)
                #pragma unroll
                for (int nt = 0; nt < NFRAG; nt++)
                    MMA_F16(acc[mt][nt], af[mt], bf[nt]);
        }
    }

    // ---- epilogue: bias (+GELU), store ----
    const int g  = lane >> 2;
    const int t4 = lane & 3;
    #pragma unroll
    for (int mt = 0; mt < 4; mt++) {
        int m = bm + wm * 64 + mt * 16 + g;
        #pragma unroll
        for (int nt = 0; nt < NFRAG; nt++) {
            int n = bn + wn * WN + nt * 8 + t4 * 2;
            float bv0 = bias[n], bv1 = bias[n + 1];
            float v0 = acc[mt][nt][0] + bv0;
            float v1 = acc[mt][nt][1] + bv1;
            float v2 = acc[mt][nt][2] + bv0;
            float v3 = acc[mt][nt][3] + bv1;
            if (GELU) {
                v0 = gelu_erf(v0); v1 = gelu_erf(v1);
                v2 = gelu_erf(v2); v3 = gelu_erf(v3);
            }
            if (HALF_OUT) {
                __half* Ch = (__half*)Cv;
                *(__half2*)&Ch[(size_t)m * N + n]       = __floats2half2_rn(v0, v1);
                *(__half2*)&Ch[(size_t)(m + 8) * N + n] = __floats2half2_rn(v2, v3);
            } else {
                float* Cf = (float*)Cv;
                *(float2*)&Cf[(size_t)m * N + n]       = make_float2(v0, v1);
                *(float2*)&Cf[(size_t)(m + 8) * N + n] = make_float2(v2, v3);
            }
        }
    }
    #undef LOADST
}

// ---------------------------------------------------------------------------
// launch
// ---------------------------------------------------------------------------
static void* sym_addr(const void* sym)
{
    void* p = nullptr;
    cudaGetSymbolAddress(&p, sym);
    return p;
}

extern "C" void kernel_launch(void* const* d_in, const int* in_sizes, int n_in,
                              void* d_out, int out_size)
{
    const float* x   = (const float*)d_in[0];
    const float* g1a = (const float*)d_in[1];
    const float* g1b = (const float*)d_in[2];
    const float* g1c = (const float*)d_in[3];
    const float* g1d = (const float*)d_in[4];
    const float* b1  = (const float*)d_in[5];
    const float* g2a = (const float*)d_in[6];
    const float* g2b = (const float*)d_in[7];
    const float* g2c = (const float*)d_in[8];
    const float* g2d = (const float*)d_in[9];
    const float* b2  = (const float*)d_in[10];
    float* out = (float*)d_out;

    float*  T12_1 = (float*)sym_addr(g_T12_1);
    float*  T34_1 = (float*)sym_addr(g_T34_1);
    float*  T12_2 = (float*)sym_addr(g_T12_2);
    float*  T34_2 = (float*)sym_addr(g_T34_2);
    float*  W1    = (float*)sym_addr(g_W1);
    float*  W2    = (float*)sym_addr(g_W2);
    __half* W1t   = (__half*)sym_addr(g_W1t);
    __half* W2t   = (__half*)sym_addr(g_W2t);
    __half* xh    = (__half*)sym_addr(g_xh);
    __half* H     = (__half*)sym_addr(g_H);

    const int SMEM1 = 1024 + NSTAGE * (8192 + 128 * 64);   // BN=128
    const int SMEM2 = 1024 + NSTAGE * (8192 +  96 * 64);   // BN=96
    cudaFuncSetAttribute(gemm_h<128, true, true>,
                         cudaFuncAttributeMaxDynamicSharedMemorySize, SMEM1);
    cudaFuncSetAttribute(gemm_h<96, false, false>,
                         cudaFuncAttributeMaxDynamicSharedMemorySize, SMEM2);

    build_tables<<<612, 256>>>(g1a, g1b, g1c, g1d, T12_1, T34_1,
                               4, 4, 6, 8, 4, 6, 8, 16);
    build_tables<<<612, 256>>>(g2a, g2b, g2c, g2d, T12_2, T34_2,
                               4, 6, 8, 16, 4, 4, 6, 8);

    {
        dim3 grid(96, 4);
        build_w<<<grid, 256>>>(T12_1, T34_1, W1, 48, 128, 24, 3072);
        build_w<<<grid, 256>>>(T12_2, T34_2, W2, 128, 48, 16, 768);
    }

    {
        dim3 blk(32, 8);
        dim3 gA(D_HID / 32, D_IN / 32);   // W1 (768x3072) -> W1t (3072x768)
        transpose_cvt_h<<<gA, blk>>>(W1, W1t, D_IN, D_HID);
        dim3 gB(D_IN / 32, D_HID / 32);   // W2 (3072x768) -> W2t (768x3072)
        transpose_cvt_h<<<gB, blk>>>(W2, W2t, D_HID, D_IN);
    }

    cvt_f2h<<<1024, 256>>>((const float4*)x, (__half2*)xh, NTOK * D_IN / 4);

    // GEMM1: H = gelu(xh @ W1 + b1)   tile 128x128, grid 24x32 = 768 CTAs
    {
        dim3 grid(D_HID / 128, NTOK / 128);
        gemm_h<128, true, true><<<grid, 256, SMEM1>>>(xh, W1t, b1, H,
                                                      NTOK, D_HID, D_IN);
    }
    // GEMM2: out = H @ W2 + b2        tile 128x96, grid 8x32 = 256 CTAs
    {
        dim3 grid(D_IN / 96, NTOK / 128);
        gemm_h<96, false, false><<<grid, 256, SMEM2>>>(H, W2t, b2, out,
                                                       NTOK, D_IN, D_HID);
    }
}

// round 10
// speedup vs baseline: 2.4824x; 1.1502x over previous
#include <cuda_runtime.h>
#include <cuda_fp16.h>
#include <cstdint>
#include <math.h>

// ---------------------------------------------------------------------------
// HybridFeedForward: TT cores -> dense W1/W2 (half, row-major [K][N]) ->
// fp16 mma.sync GEMMs with B row-major via ldmatrix.trans.
//   GEMM1: H = gelu(x @ W1 + b1)   (4096 x 3072, K=768)   tile 128x128
//   GEMM2: y = H @ W2 + b2         (4096 x 768,  K=3072)  tile 128x96
// ---------------------------------------------------------------------------

#define NTOK 4096
#define D_IN 768
#define D_HID 3072
#define NSTAGE 4

// ---- scratch (device globals; no allocation allowed) ----
__device__ float  g_T12_1[384 * 24];
__device__ float  g_T34_1[24 * 6144];
__device__ float  g_T12_2[384 * 24];
__device__ float  g_T34_2[24 * 6144];
__device__ __half g_W1h[D_IN * D_HID];     // W1 [768][3072] half (row-major K x N)
__device__ __half g_W2h[D_HID * D_IN];     // W2 [3072][768] half
__device__ __half g_xh[NTOK * D_IN];       // x in half
__device__ __half g_H[NTOK * D_HID];       // hidden, half

// ---------------------------------------------------------------------------
// helpers
// ---------------------------------------------------------------------------
__device__ __forceinline__ float gelu_erf(float x)
{
    return 0.5f * x * (1.0f + erff(x * 0.70710678118654752f));
}

__device__ __forceinline__ uint32_t smem_u32(const void* p)
{
    uint32_t a;
    asm("{ .reg .u64 t; cvta.to.shared.u64 t, %1; cvt.u32.u64 %0, t; }"
        : "=r"(a) : "l"(p));
    return a;
}

// ---------------------------------------------------------------------------
// Stage 1: TT core contraction tables
// ---------------------------------------------------------------------------
__global__ void build_tables(const float* __restrict__ g1, const float* __restrict__ g2,
                             const float* __restrict__ g3, const float* __restrict__ g4,
                             float* __restrict__ T12, float* __restrict__ T34,
                             int I1, int I2, int I3, int I4,
                             int O1, int O2, int O3, int O4)
{
    const int R1 = 12, R2 = 24, R3 = 12;
    int idx = blockIdx.x * blockDim.x + threadIdx.x;
    int n12 = I1 * I2 * O1 * O2 * R2;     // 9216
    int nN  = I3 * I4 * O3 * O4;          // 6144
    if (idx < n12) {
        int r2 = idx % R2; int m = idx / R2;
        int o2 = m % O2; int t = m / O2;
        int o1 = t % O1; t /= O1;
        int i2 = t % I2; int i1 = t / I2;
        float a0 = 0.f, a1 = 0.f, a2 = 0.f, a3 = 0.f;
        #pragma unroll
        for (int r1 = 0; r1 < R1; r1 += 4) {
            a0 += g1[(i1 * O1 + o1) * R1 + r1 + 0] * g2[(((r1 + 0) * I2 + i2) * O2 + o2) * R2 + r2];
            a1 += g1[(i1 * O1 + o1) * R1 + r1 + 1] * g2[(((r1 + 1) * I2 + i2) * O2 + o2) * R2 + r2];
            a2 += g1[(i1 * O1 + o1) * R1 + r1 + 2] * g2[(((r1 + 2) * I2 + i2) * O2 + o2) * R2 + r2];
            a3 += g1[(i1 * O1 + o1) * R1 + r1 + 3] * g2[(((r1 + 3) * I2 + i2) * O2 + o2) * R2 + r2];
        }
        T12[m * R2 + r2] = (a0 + a1) + (a2 + a3);
    } else {
        int j = idx - n12;
        if (j >= R2 * nN) return;
        int n = j % nN; int r2 = j / nN;
        int o4 = n % O4; int t = n / O4;
        int o3 = t % O3; t /= O3;
        int i4 = t % I4; int i3 = t / I4;
        float a0 = 0.f, a1 = 0.f, a2 = 0.f, a3 = 0.f;
        #pragma unroll
        for (int r3 = 0; r3 < R3; r3 += 4) {
            a0 += g3[((r2 * I3 + i3) * O3 + o3) * R3 + r3 + 0] * g4[((r3 + 0) * I4 + i4) * O4 + o4];
            a1 += g3[((r2 * I3 + i3) * O3 + o3) * R3 + r3 + 1] * g4[((r3 + 1) * I4 + i4) * O4 + o4];
            a2 += g3[((r2 * I3 + i3) * O3 + o3) * R3 + r3 + 2] * g4[((r3 + 2) * I4 + i4) * O4 + o4];
            a3 += g3[((r2 * I3 + i3) * O3 + o3) * R3 + r3 + 3] * g4[((r3 + 3) * I4 + i4) * O4 + o4];
        }
        T34[r2 * nN + n] = (a0 + a1) + (a2 + a3);
    }
}

// ---------------------------------------------------------------------------
// Stage 2 (both layers in one launch, blockIdx.z selects layer):
//   Wh[row, col] = half( sum_r2 T12[m,r2] * T34[r2,n] )   row-major [K][N]
// ---------------------------------------------------------------------------
__global__ void __launch_bounds__(256)
build_w2x(const float* __restrict__ T12a, const float* __restrict__ T34a,
          __half* __restrict__ Wa,
          const float* __restrict__ T12b, const float* __restrict__ T34b,
          __half* __restrict__ Wb)
{
    const float* T12;
    const float* T34;
    __half* W;
    int I34, O34, O12, Ncols;
    if (blockIdx.z == 0) {
        T12 = T12a; T34 = T34a; W = Wa;
        I34 = 48; O34 = 128; O12 = 24; Ncols = 3072;
    } else {
        T12 = T12b; T34 = T34b; W = Wb;
        I34 = 128; O34 = 48; O12 = 16; Ncols = 768;
    }

    __shared__ float s12[96 * 24];
    int mbase = blockIdx.y * 96;
    for (int i = threadIdx.x; i < 96 * 24 / 4; i += 256)
        ((float4*)s12)[i] = ((const float4*)(T12 + mbase * 24))[i];
    __syncthreads();

    int nl = threadIdx.x & 63;
    int mg = threadIdx.x >> 6;
    int n  = blockIdx.x * 64 + nl;

    float t34[24];
    #pragma unroll
    for (int r = 0; r < 24; r++) t34[r] = T34[r * 6144 + n];

    int i3i4 = n / O34, o3o4 = n % O34;

    int m0    = mbase + mg * 24;
    int i1i2  = m0 / O12;
    int o1o2  = m0 % O12;
    long addr = (long)(i1i2 * I34 + i3i4) * Ncols + o1o2 * O34 + o3o4;
    const long dWrap = (long)I34 * Ncols - (long)(O12 - 1) * O34;

    const float4* p = (const float4*)&s12[(mg * 24) * 24];
    #pragma unroll 4
    for (int mm = 0; mm < 24; mm++) {
        float a0 = 0.f, a1 = 0.f, a2 = 0.f, a3 = 0.f;
        #pragma unroll
        for (int q = 0; q < 6; q++) {
            float4 v = p[q];
            a0 += v.x * t34[q * 4 + 0];
            a1 += v.y * t34[q * 4 + 1];
            a2 += v.z * t34[q * 4 + 2];
            a3 += v.w * t34[q * 4 + 3];
        }
        p += 6;
        W[addr] = __float2half_rn((a0 + a1) + (a2 + a3));
        o1o2++;
        if (o1o2 == O12) { o1o2 = 0; addr += dWrap; }
        else             { addr += O34; }
    }
}

// ---------------------------------------------------------------------------
// fp32 -> fp16 vector convert (x)
// ---------------------------------------------------------------------------
__global__ void cvt_f2h(const float4* __restrict__ in, __half2* __restrict__ out, int n4)
{
    int i = blockIdx.x * blockDim.x + threadIdx.x;
    for (; i < n4; i += gridDim.x * blockDim.x) {
        float4 v = in[i];
        out[2 * i + 0] = __floats2half2_rn(v.x, v.y);
        out[2 * i + 1] = __floats2half2_rn(v.z, v.w);
    }
}

// ---------------------------------------------------------------------------
// fp16 GEMM: C = act(A @ B + bias)
//   A: M x K row-major half;  B: K x N row-major half (ldmatrix.trans path)
//   CTA tile 128 x BN, BK=32, 4-stage cp.async, 8 warps (2m x 4n).
// smem per stage:
//   A[128][32] half, 64B rows, chunk swizzle  c ^= (row>>1)&3
//   B[32 rows][256B], 16B chunk swizzle       c ^= (k&7)      (BN<=128)
// ---------------------------------------------------------------------------
#define MMA_F16(d, a, b)                                                      \
    asm volatile("mma.sync.aligned.m16n8k16.row.col.f32.f16.f16.f32 "         \
                 "{%0,%1,%2,%3}, {%4,%5,%6,%7}, {%8,%9}, {%0,%1,%2,%3};"      \
                 : "+f"(d[0]), "+f"(d[1]), "+f"(d[2]), "+f"(d[3])             \
                 : "r"(a[0]), "r"(a[1]), "r"(a[2]), "r"(a[3]),                \
                   "r"(b[0]), "r"(b[1]))

#define LDSM_X4(r0, r1, r2, r3, addr)                                         \
    asm volatile("ldmatrix.sync.aligned.m8n8.x4.shared.b16 {%0,%1,%2,%3}, [%4];" \
                 : "=r"(r0), "=r"(r1), "=r"(r2), "=r"(r3) : "r"(addr))

#define LDSM_X4T(r0, r1, r2, r3, addr)                                        \
    asm volatile("ldmatrix.sync.aligned.m8n8.x4.trans.shared.b16 {%0,%1,%2,%3}, [%4];" \
                 : "=r"(r0), "=r"(r1), "=r"(r2), "=r"(r3) : "r"(addr))

#define LDSM_X2T(r0, r1, addr)                                                \
    asm volatile("ldmatrix.sync.aligned.m8n8.x2.trans.shared.b16 {%0,%1}, [%2];" \
                 : "=r"(r0), "=r"(r1) : "r"(addr))

template <int BN, bool GELU, bool HALF_OUT>
__global__ void __launch_bounds__(256, 2)
gemm_h(const __half* __restrict__ A, const __half* __restrict__ B,
       const float* __restrict__ bias, void* __restrict__ Cv,
       int M, int N, int K)
{
    constexpr int SBYTES = 8192 + 8192;      // A stage + B stage (B rows padded 256B)
    constexpr int NFRAG  = BN / 32;          // n-fragments (8 wide) per warp
    constexpr int WN     = BN / 4;           // warp n-tile

    extern __shared__ char dsm[];
    uint32_t stg = (smem_u32(dsm) + 1023) & ~1023u;

    const int tid  = threadIdx.x;
    const int lane = tid & 31;
    const int wid  = tid >> 5;
    const int wm   = wid & 1;          // 2 warps along M (64 each)
    const int wn   = wid >> 1;         // 4 warps along N (WN each)
    const int bm   = blockIdx.y * 128;
    const int bn   = blockIdx.x * BN;
    const int T    = K >> 5;

    // ---- A global->smem: row = tid>>1, two 16B chunks each ----
    const int a_rowl = tid >> 1;
    const int jj     = tid & 1;
    const uint32_t swa = (a_rowl >> 1) & 3;
    const __half* Ag = A + (size_t)(bm + a_rowl) * K;
    uint32_t a_st[2];
    #pragma unroll
    for (int q = 0; q < 2; q++) {
        uint32_t c = (jj << 1) + q;
        a_st[q] = a_rowl * 64 + ((c ^ swa) << 4);
    }

    // ---- B global->smem: rows are k (32 per tile), row-major N ----
    // BN==128: kr = tid>>3, chunks c = (tid&7)*2 + q          (16 chunks/row)
    // BN==96 : part0 kr = tid>>3, c = tid&7 ; part1 (tid<128) kr = tid>>2, c = 8+(tid&3)
    const int b_kr0 = tid >> 3;
    const int b_kr1 = tid >> 2;                 // BN==96 part1
    const __half* Bg0 = B + (size_t)b_kr0 * N + bn;
    const __half* Bg1 = B + (size_t)b_kr1 * N + bn;

    #define LOADST(t, s)                                                           \
    do {                                                                           \
        uint32_t sa = stg + (s) * SBYTES;                                          \
        uint32_t sb = sa + 8192;                                                   \
        const __half* ap = Ag + (t) * 32 + (jj << 1) * 8;                          \
        _Pragma("unroll")                                                          \
        for (int q = 0; q < 2; q++)                                                \
            asm volatile("cp.async.cg.shared.global [%0], [%1], 16;"               \
                         :: "r"(sa + a_st[q]), "l"(ap + q * 8) : "memory");        \
        const __half* bp = Bg0 + (size_t)(t) * 32 * N;                             \
        if (BN == 128) {                                                           \
            _Pragma("unroll")                                                      \
            for (int q = 0; q < 2; q++) {                                          \
                uint32_t c = ((tid & 7) << 1) + q;                                 \
                asm volatile("cp.async.cg.shared.global [%0], [%1], 16;"           \
                    :: "r"(sb + b_kr0 * 256 + ((c ^ (b_kr0 & 7)) << 4)),           \
                       "l"(bp + c * 8) : "memory");                                \
            }                                                                      \
        } else {                                                                   \
            uint32_t c = tid & 7;                                                  \
            asm volatile("cp.async.cg.shared.global [%0], [%1], 16;"               \
                :: "r"(sb + b_kr0 * 256 + ((c ^ (b_kr0 & 7)) << 4)),               \
                   "l"(bp + c * 8) : "memory");                                    \
            if (tid < 128) {                                                       \
                uint32_t c2 = 8 + (tid & 3);                                       \
                const __half* bp1 = Bg1 + (size_t)(t) * 32 * N;                    \
                asm volatile("cp.async.cg.shared.global [%0], [%1], 16;"           \
                    :: "r"(sb + b_kr1 * 256 + ((c2 ^ (b_kr1 & 7)) << 4)),          \
                       "l"(bp1 + c2 * 8) : "memory");                              \
            }                                                                      \
        }                                                                          \
    } while (0)

    // ---- A fragment address components (unchanged, validated) ----
    const int lr      = lane & 7;
    const int mi      = lane >> 3;
    const int a_row0  = wm * 64 + ((mi & 1) << 3) + lr;
    const int a_kcbit = (mi >> 1) & 1;

    // ---- B fragment (ldmatrix.trans) per-lane components ----
    const int b_kl = ((lane >> 3) & 1) * 8 + (lane & 7);   // k within 16
    const int b_j2 = (lane >> 4) & 1;                      // n +8 (x4 only)

    float acc[4][NFRAG][4];
    #pragma unroll
    for (int i = 0; i < 4; i++)
        #pragma unroll
        for (int j = 0; j < NFRAG; j++)
            #pragma unroll
            for (int k = 0; k < 4; k++) acc[i][j][k] = 0.f;

    // ---- prologue ----
    #pragma unroll
    for (int s = 0; s < NSTAGE - 1; s++) {
        LOADST(s, s);
        asm volatile("cp.async.commit_group;" ::: "memory");
    }

    for (int t = 0; t < T; t++) {
        asm volatile("cp.async.wait_group %0;" :: "n"(NSTAGE - 2) : "memory");
        __syncthreads();

        int tl = t + NSTAGE - 1;
        if (tl < T) LOADST(tl, tl & (NSTAGE - 1));
        asm volatile("cp.async.commit_group;" ::: "memory");

        uint32_t sa = stg + (t & (NSTAGE - 1)) * SBYTES;
        uint32_t sb = sa + 8192;

        #pragma unroll
        for (int ks = 0; ks < 2; ks++) {
            uint32_t af[4][4];
            #pragma unroll
            for (int mt = 0; mt < 4; mt++) {
                int r = a_row0 + mt * 16;
                uint32_t kc = (uint32_t)((ks << 1) | a_kcbit);
                uint32_t addr = sa + r * 64 + ((kc ^ ((r >> 1) & 3)) << 4);
                LDSM_X4(af[mt][0], af[mt][1], af[mt][2], af[mt][3], addr);
            }
            uint32_t bf[NFRAG][2];
            {
                int kk = ks * 16 + b_kl;
                #pragma unroll
                for (int p = 0; p < NFRAG / 2; p++) {
                    uint32_t c = (uint32_t)(((wn * WN + p * 16) >> 3) + b_j2);
                    uint32_t addr = sb + kk * 256 + ((c ^ (uint32_t)(kk & 7)) << 4);
                    uint32_t r0, r1, r2, r3;
                    LDSM_X4T(r0, r1, r2, r3, addr);
                    bf[2 * p][0] = r0;     bf[2 * p][1] = r1;
                    bf[2 * p + 1][0] = r2; bf[2 * p + 1][1] = r3;
                }
                if (NFRAG & 1) {
                    uint32_t c = (uint32_t)((wn * WN + (NFRAG - 1) * 8) >> 3);
                    uint32_t addr = sb + kk * 256 + ((c ^ (uint32_t)(kk & 7)) << 4);
                    LDSM_X2T(bf[NFRAG - 1][0], bf[NFRAG - 1][1], addr);
                }
            }
            #pragma unroll
            for (int mt = 0; mt < 4; mt++)
                #pragma unroll
                for (int nt = 0; nt < NFRAG; nt++)
                    MMA_F16(acc[mt][nt], af[mt], bf[nt]);
        }
    }

    // ---- epilogue: bias (+GELU), store ----
    const int g  = lane >> 2;
    const int t4 = lane & 3;
    #pragma unroll
    for (int mt = 0; mt < 4; mt++) {
        int m = bm + wm * 64 + mt * 16 + g;
        #pragma unroll
        for (int nt = 0; nt < NFRAG; nt++) {
            int n = bn + wn * WN + nt * 8 + t4 * 2;
            float bv0 = bias[n], bv1 = bias[n + 1];
            float v0 = acc[mt][nt][0] + bv0;
            float v1 = acc[mt][nt][1] + bv1;
            float v2 = acc[mt][nt][2] + bv0;
            float v3 = acc[mt][nt][3] + bv1;
            if (GELU) {
                v0 = gelu_erf(v0); v1 = gelu_erf(v1);
                v2 = gelu_erf(v2); v3 = gelu_erf(v3);
            }
            if (HALF_OUT) {
                __half* Ch = (__half*)Cv;
                *(__half2*)&Ch[(size_t)m * N + n]       = __floats2half2_rn(v0, v1);
                *(__half2*)&Ch[(size_t)(m + 8) * N + n] = __floats2half2_rn(v2, v3);
            } else {
                float* Cf = (float*)Cv;
                *(float2*)&Cf[(size_t)m * N + n]       = make_float2(v0, v1);
                *(float2*)&Cf[(size_t)(m + 8) * N + n] = make_float2(v2, v3);
            }
        }
    }
    #undef LOADST
}

// ---------------------------------------------------------------------------
// launch
// ---------------------------------------------------------------------------
static void* sym_addr(const void* sym)
{
    void* p = nullptr;
    cudaGetSymbolAddress(&p, sym);
    return p;
}

extern "C" void kernel_launch(void* const* d_in, const int* in_sizes, int n_in,
                              void* d_out, int out_size)
{
    const float* x   = (const float*)d_in[0];
    const float* g1a = (const float*)d_in[1];
    const float* g1b = (const float*)d_in[2];
    const float* g1c = (const float*)d_in[3];
    const float* g1d = (const float*)d_in[4];
    const float* b1  = (const float*)d_in[5];
    const float* g2a = (const float*)d_in[6];
    const float* g2b = (const float*)d_in[7];
    const float* g2c = (const float*)d_in[8];
    const float* g2d = (const float*)d_in[9];
    const float* b2  = (const float*)d_in[10];
    float* out = (float*)d_out;

    float*  T12_1 = (float*)sym_addr(g_T12_1);
    float*  T34_1 = (float*)sym_addr(g_T34_1);
    float*  T12_2 = (float*)sym_addr(g_T12_2);
    float*  T34_2 = (float*)sym_addr(g_T34_2);
    __half* W1h   = (__half*)sym_addr(g_W1h);
    __half* W2h   = (__half*)sym_addr(g_W2h);
    __half* xh    = (__half*)sym_addr(g_xh);
    __half* H     = (__half*)sym_addr(g_H);

    const int SMEM = 1024 + NSTAGE * 16384;   // 66.5 KB (both GEMMs)
    cudaFuncSetAttribute(gemm_h<128, true, true>,
                         cudaFuncAttributeMaxDynamicSharedMemorySize, SMEM);
    cudaFuncSetAttribute(gemm_h<96, false, false>,
                         cudaFuncAttributeMaxDynamicSharedMemorySize, SMEM);

    build_tables<<<612, 256>>>(g1a, g1b, g1c, g1d, T12_1, T34_1,
                               4, 4, 6, 8, 4, 6, 8, 16);
    build_tables<<<612, 256>>>(g2a, g2b, g2c, g2d, T12_2, T34_2,
                               4, 6, 8, 16, 4, 4, 6, 8);

    // Both W builds in one launch: W1h [768][3072], W2h [3072][768] (half)
    {
        dim3 grid(96, 4, 2);
        build_w2x<<<grid, 256>>>(T12_1, T34_1, W1h, T12_2, T34_2, W2h);
    }

    cvt_f2h<<<1024, 256>>>((const float4*)x, (__half2*)xh, NTOK * D_IN / 4);

    // GEMM1: H = gelu(xh @ W1 + b1)   tile 128x128, grid 24x32 = 768 CTAs
    {
        dim3 grid(D_HID / 128, NTOK / 128);
        gemm_h<128, true, true><<<grid, 256, SMEM>>>(xh, W1h, b1, H,
                                                     NTOK, D_HID, D_IN);
    }
    // GEMM2: out = H @ W2 + b2        tile 128x96, grid 8x32 = 256 CTAs
    {
        dim3 grid(D_IN / 96, NTOK / 128);
        gemm_h<96, false, false><<<grid, 256, SMEM>>>(H, W2h, b2, out,
                                                      NTOK, D_IN, D_HID);
    }
}